// round 4
// baseline (speedup 1.0000x reference)
#include <cuda_runtime.h>
#include <cstdint>

#define NN 50000
#define NE 800000
#define DD 128

// scratch (static device globals — no allocation allowed)
__device__ float g_accum[NN * DD];   // 25.6 MB scatter accumulator
__device__ float g_cnt[NN];          // in-degree counts
__device__ float g_x[NN * DD];       // (1+eps)*hidden + aggr
__device__ float g_h[NN * DD];       // after first GEMM + relu

// ---------------------------------------------------------------------------
// K1: zero accumulator + counts
// ---------------------------------------------------------------------------
__global__ void zero_kernel() {
    int i = blockIdx.x * blockDim.x + threadIdx.x;
    const int tot4 = (NN * DD) / 4;   // 1.6M float4
    if (i < tot4) ((float4*)g_accum)[i] = make_float4(0.f, 0.f, 0.f, 0.f);
    if (i < NN)   g_cnt[i] = 0.f;
}

// ---------------------------------------------------------------------------
// K2: edge scatter. One warp per edge; each lane handles 4 contiguous dims.
// msg = relu(hidden[src] + a*We + be); 4 scalar atomicAdds into g_accum[dst].
// edge_index is int32 in memory (JAX x64-disabled downcasts int64 -> int32).
// ---------------------------------------------------------------------------
__global__ void scatter_kernel(const float* __restrict__ hidden,
                               const int* __restrict__ edge_index,
                               const float* __restrict__ edge_attr,
                               const float* __restrict__ We,
                               const float* __restrict__ be) {
    int gtid = blockIdx.x * blockDim.x + threadIdx.x;
    int e    = gtid >> 5;
    int lane = gtid & 31;
    if (e >= NE) return;

    int   src = __ldg(&edge_index[e]);
    int   dst = __ldg(&edge_index[NE + e]);
    float a   = __ldg(&edge_attr[e]);

    int d0 = lane * 4;
    float4 h  = *(const float4*)&hidden[(size_t)src * DD + d0];
    float4 w  = *(const float4*)&We[d0];
    float4 b  = *(const float4*)&be[d0];

    float4 m;
    m.x = fmaxf(fmaf(a, w.x, b.x) + h.x, 0.f);
    m.y = fmaxf(fmaf(a, w.y, b.y) + h.y, 0.f);
    m.z = fmaxf(fmaf(a, w.z, b.z) + h.z, 0.f);
    m.w = fmaxf(fmaf(a, w.w, b.w) + h.w, 0.f);

    float* p = &g_accum[(size_t)dst * DD + d0];
    atomicAdd(p + 0, m.x);
    atomicAdd(p + 1, m.y);
    atomicAdd(p + 2, m.z);
    atomicAdd(p + 3, m.w);

    if (lane == 0) atomicAdd(&g_cnt[dst], 1.0f);
}

// ---------------------------------------------------------------------------
// K3: x = (1+eps)*hidden + accum / max(cnt,1)   (writes g_x directly)
// ---------------------------------------------------------------------------
__global__ void finalize_kernel(const float* __restrict__ hidden,
                                const float* __restrict__ eps) {
    int i = blockIdx.x * blockDim.x + threadIdx.x;
    const int tot4 = (NN * DD) / 4;
    if (i >= tot4) return;
    int row = i >> 5;                          // 32 float4 per row
    float inv = 1.0f / fmaxf(g_cnt[row], 1.0f);
    float s   = 1.0f + eps[0];
    float4 h  = ((const float4*)hidden)[i];
    float4 a  = ((const float4*)g_accum)[i];
    float4 o;
    o.x = fmaf(s, h.x, a.x * inv);
    o.y = fmaf(s, h.y, a.y * inv);
    o.z = fmaf(s, h.z, a.z * inv);
    o.w = fmaf(s, h.w, a.w * inv);
    ((float4*)g_x)[i] = o;
}

// ---------------------------------------------------------------------------
// K4/K5: C = act(A @ W + bias), A[M,128], W[128,128] (stored [in,out]).
// TILE_M=64, 256 threads, KT=32. Warp w -> rows w*8..w*8+7, lane l -> cols l*4..+3.
// ---------------------------------------------------------------------------
template <bool RELU>
__global__ void gemm128_kernel(const float* __restrict__ A,
                               const float* __restrict__ W,
                               const float* __restrict__ bias,
                               float* __restrict__ C, int M) {
    __shared__ float As[64][32];
    __shared__ float Ws[32][128];

    int tid  = threadIdx.x;
    int warp = tid >> 5;
    int lane = tid & 31;
    int row0 = blockIdx.x * 64;
    int r0   = warp * 8;
    int c0   = lane * 4;

    float acc[8][4];
#pragma unroll
    for (int i = 0; i < 8; i++)
#pragma unroll
        for (int j = 0; j < 4; j++) acc[i][j] = 0.f;

    for (int kt = 0; kt < 4; kt++) {
        // load A tile: 64 rows x 32 k  (512 float4)
#pragma unroll
        for (int idx = tid; idx < 512; idx += 256) {
            int r = idx >> 3, f = idx & 7;
            int grow = row0 + r;
            float4 v = make_float4(0.f, 0.f, 0.f, 0.f);
            if (grow < M) v = *(const float4*)&A[grow * DD + kt * 32 + f * 4];
            *(float4*)&As[r][f * 4] = v;
        }
        // load W tile: 32 k-rows x 128 cols (1024 float4)
#pragma unroll
        for (int idx = tid; idx < 1024; idx += 256) {
            int r = idx >> 5, f = idx & 31;
            *(float4*)&Ws[r][f * 4] = *(const float4*)&W[(kt * 32 + r) * DD + f * 4];
        }
        __syncthreads();

#pragma unroll
        for (int kk = 0; kk < 32; kk++) {
            float4 b = *(float4*)&Ws[kk][c0];
#pragma unroll
            for (int i = 0; i < 8; i++) {
                float a = As[r0 + i][kk];
                acc[i][0] = fmaf(a, b.x, acc[i][0]);
                acc[i][1] = fmaf(a, b.y, acc[i][1]);
                acc[i][2] = fmaf(a, b.z, acc[i][2]);
                acc[i][3] = fmaf(a, b.w, acc[i][3]);
            }
        }
        __syncthreads();
    }

    float4 bb = *(const float4*)&bias[c0];
#pragma unroll
    for (int i = 0; i < 8; i++) {
        int row = row0 + r0 + i;
        if (row < M) {
            float4 o;
            o.x = acc[i][0] + bb.x;
            o.y = acc[i][1] + bb.y;
            o.z = acc[i][2] + bb.z;
            o.w = acc[i][3] + bb.w;
            if (RELU) {
                o.x = fmaxf(o.x, 0.f);
                o.y = fmaxf(o.y, 0.f);
                o.z = fmaxf(o.z, 0.f);
                o.w = fmaxf(o.w, 0.f);
            }
            *(float4*)&C[row * DD + c0] = o;
        }
    }
}

// ---------------------------------------------------------------------------
extern "C" void kernel_launch(void* const* d_in, const int* in_sizes, int n_in,
                              void* d_out, int out_size) {
    const float* hidden = (const float*)d_in[0];
    const int*   eidx   = (const int*)d_in[1];
    const float* eattr  = (const float*)d_in[2];
    const float* We     = (const float*)d_in[3];
    const float* be     = (const float*)d_in[4];
    const float* W1     = (const float*)d_in[5];
    const float* b1     = (const float*)d_in[6];
    const float* W2     = (const float*)d_in[7];
    const float* b2     = (const float*)d_in[8];
    const float* eps    = (const float*)d_in[9];
    float*       out    = (float*)d_out;

    // Resolve DEVICE addresses of the scratch globals. Taking &g_x in host
    // code yields the host shadow symbol (silently dereferenceable on GB300
    // via ATS -> reads zeros); cudaGetSymbolAddress gives the real device ptr.
    float *p_x = nullptr, *p_h = nullptr;
    cudaGetSymbolAddress((void**)&p_x, g_x);
    cudaGetSymbolAddress((void**)&p_h, g_h);

    const int tot4 = (NN * DD) / 4;                 // 1.6M
    zero_kernel<<<(tot4 + 255) / 256, 256>>>();

    scatter_kernel<<<(NE * 32) / 256, 256>>>(hidden, eidx, eattr, We, be);

    finalize_kernel<<<(tot4 + 255) / 256, 256>>>(hidden, eps);

    int gblocks = (NN + 63) / 64;                   // 782
    gemm128_kernel<true ><<<gblocks, 256>>>(p_x, W1, b1, p_h, NN);
    gemm128_kernel<false><<<gblocks, 256>>>(p_h, W2, b2, out, NN);
}

// round 5
// speedup vs baseline: 1.5672x; 1.5672x over previous
#include <cuda_runtime.h>
#include <cstdint>

#define NN 50000
#define NE 800000
#define DD 128

// scratch (static device globals — no allocation allowed)
__device__ float g_accum[NN * DD];   // 25.6 MB scatter accumulator
__device__ float g_cnt[NN];          // in-degree counts
__device__ float g_h[NN * DD];       // after first GEMM + relu

// ---------------------------------------------------------------------------
// K1: zero accumulator + counts
// ---------------------------------------------------------------------------
__global__ void zero_kernel() {
    int i = blockIdx.x * blockDim.x + threadIdx.x;
    const int tot4 = (NN * DD) / 4;   // 1.6M float4
    if (i < tot4) ((float4*)g_accum)[i] = make_float4(0.f, 0.f, 0.f, 0.f);
    if (i < NN)   g_cnt[i] = 0.f;
}

// ---------------------------------------------------------------------------
// K2: edge scatter. One warp per edge; each lane handles 4 contiguous dims.
// msg = relu(hidden[src] + a*We + be); one red.v4 per lane into g_accum[dst].
// edge_index is int32 in memory (JAX x64-disabled downcasts int64 -> int32).
// ---------------------------------------------------------------------------
__global__ void scatter_kernel(const float* __restrict__ hidden,
                               const int* __restrict__ edge_index,
                               const float* __restrict__ edge_attr,
                               const float* __restrict__ We,
                               const float* __restrict__ be) {
    int gtid = blockIdx.x * blockDim.x + threadIdx.x;
    int e    = gtid >> 5;
    int lane = gtid & 31;
    if (e >= NE) return;

    int   src = __ldg(&edge_index[e]);
    int   dst = __ldg(&edge_index[NE + e]);
    float a   = __ldg(&edge_attr[e]);

    int d0 = lane * 4;
    float4 h  = *(const float4*)&hidden[(size_t)src * DD + d0];
    float4 w  = *(const float4*)&We[d0];
    float4 b  = *(const float4*)&be[d0];

    float4 m;
    m.x = fmaxf(fmaf(a, w.x, b.x) + h.x, 0.f);
    m.y = fmaxf(fmaf(a, w.y, b.y) + h.y, 0.f);
    m.z = fmaxf(fmaf(a, w.z, b.z) + h.z, 0.f);
    m.w = fmaxf(fmaf(a, w.w, b.w) + h.w, 0.f);

    unsigned long long p =
        (unsigned long long)__cvta_generic_to_global(&g_accum[(size_t)dst * DD + d0]);
    asm volatile("red.global.add.v4.f32 [%0], {%1,%2,%3,%4};"
                 :: "l"(p), "f"(m.x), "f"(m.y), "f"(m.z), "f"(m.w)
                 : "memory");

    if (lane == 0) atomicAdd(&g_cnt[dst], 1.0f);
}

// ---------------------------------------------------------------------------
// K3: GEMM1 fused with finalize: A_row = (1+eps)*hidden + accum/max(cnt,1),
// C = relu(A @ W1 + b1). TILE_M=64, 256 threads, KT=32.
// ---------------------------------------------------------------------------
__global__ void gemm128_fused_kernel(const float* __restrict__ hidden,
                                     const float* __restrict__ eps,
                                     const float* __restrict__ W,
                                     const float* __restrict__ bias,
                                     float* __restrict__ C, int M) {
    __shared__ float As[64][32];
    __shared__ float Ws[32][128];

    int tid  = threadIdx.x;
    int warp = tid >> 5;
    int lane = tid & 31;
    int row0 = blockIdx.x * 64;
    int r0   = warp * 8;
    int c0   = lane * 4;

    float s = 1.0f + __ldg(&eps[0]);

    float acc[8][4];
#pragma unroll
    for (int i = 0; i < 8; i++)
#pragma unroll
        for (int j = 0; j < 4; j++) acc[i][j] = 0.f;

    for (int kt = 0; kt < 4; kt++) {
        // load + finalize A tile: 64 rows x 32 k  (512 float4)
#pragma unroll
        for (int idx = tid; idx < 512; idx += 256) {
            int r = idx >> 3, f = idx & 7;
            int grow = row0 + r;
            float4 v = make_float4(0.f, 0.f, 0.f, 0.f);
            if (grow < M) {
                size_t off = (size_t)grow * DD + kt * 32 + f * 4;
                float inv  = 1.0f / fmaxf(g_cnt[grow], 1.0f);
                float4 h   = *(const float4*)&hidden[off];
                float4 a   = *(const float4*)&g_accum[off];
                v.x = fmaf(s, h.x, a.x * inv);
                v.y = fmaf(s, h.y, a.y * inv);
                v.z = fmaf(s, h.z, a.z * inv);
                v.w = fmaf(s, h.w, a.w * inv);
            }
            *(float4*)&As[r][f * 4] = v;
        }
        // load W tile: 32 k-rows x 128 cols (1024 float4)
#pragma unroll
        for (int idx = tid; idx < 1024; idx += 256) {
            int r = idx >> 5, f = idx & 31;
            *(float4*)&Ws[r][f * 4] = *(const float4*)&W[(kt * 32 + r) * DD + f * 4];
        }
        __syncthreads();

#pragma unroll
        for (int kk = 0; kk < 32; kk++) {
            float4 b = *(float4*)&Ws[kk][c0];
#pragma unroll
            for (int i = 0; i < 8; i++) {
                float a = As[r0 + i][kk];
                acc[i][0] = fmaf(a, b.x, acc[i][0]);
                acc[i][1] = fmaf(a, b.y, acc[i][1]);
                acc[i][2] = fmaf(a, b.z, acc[i][2]);
                acc[i][3] = fmaf(a, b.w, acc[i][3]);
            }
        }
        __syncthreads();
    }

    float4 bb = *(const float4*)&bias[c0];
#pragma unroll
    for (int i = 0; i < 8; i++) {
        int row = row0 + r0 + i;
        if (row < M) {
            float4 o;
            o.x = fmaxf(acc[i][0] + bb.x, 0.f);
            o.y = fmaxf(acc[i][1] + bb.y, 0.f);
            o.z = fmaxf(acc[i][2] + bb.z, 0.f);
            o.w = fmaxf(acc[i][3] + bb.w, 0.f);
            *(float4*)&C[row * DD + c0] = o;
        }
    }
}

// ---------------------------------------------------------------------------
// K4: plain GEMM2: C = A @ W2 + b2 (no activation)
// ---------------------------------------------------------------------------
__global__ void gemm128_kernel(const float* __restrict__ A,
                               const float* __restrict__ W,
                               const float* __restrict__ bias,
                               float* __restrict__ C, int M) {
    __shared__ float As[64][32];
    __shared__ float Ws[32][128];

    int tid  = threadIdx.x;
    int warp = tid >> 5;
    int lane = tid & 31;
    int row0 = blockIdx.x * 64;
    int r0   = warp * 8;
    int c0   = lane * 4;

    float acc[8][4];
#pragma unroll
    for (int i = 0; i < 8; i++)
#pragma unroll
        for (int j = 0; j < 4; j++) acc[i][j] = 0.f;

    for (int kt = 0; kt < 4; kt++) {
#pragma unroll
        for (int idx = tid; idx < 512; idx += 256) {
            int r = idx >> 3, f = idx & 7;
            int grow = row0 + r;
            float4 v = make_float4(0.f, 0.f, 0.f, 0.f);
            if (grow < M) v = *(const float4*)&A[(size_t)grow * DD + kt * 32 + f * 4];
            *(float4*)&As[r][f * 4] = v;
        }
#pragma unroll
        for (int idx = tid; idx < 1024; idx += 256) {
            int r = idx >> 5, f = idx & 31;
            *(float4*)&Ws[r][f * 4] = *(const float4*)&W[(kt * 32 + r) * DD + f * 4];
        }
        __syncthreads();

#pragma unroll
        for (int kk = 0; kk < 32; kk++) {
            float4 b = *(float4*)&Ws[kk][c0];
#pragma unroll
            for (int i = 0; i < 8; i++) {
                float a = As[r0 + i][kk];
                acc[i][0] = fmaf(a, b.x, acc[i][0]);
                acc[i][1] = fmaf(a, b.y, acc[i][1]);
                acc[i][2] = fmaf(a, b.z, acc[i][2]);
                acc[i][3] = fmaf(a, b.w, acc[i][3]);
            }
        }
        __syncthreads();
    }

    float4 bb = *(const float4*)&bias[c0];
#pragma unroll
    for (int i = 0; i < 8; i++) {
        int row = row0 + r0 + i;
        if (row < M) {
            float4 o;
            o.x = acc[i][0] + bb.x;
            o.y = acc[i][1] + bb.y;
            o.z = acc[i][2] + bb.z;
            o.w = acc[i][3] + bb.w;
            *(float4*)&C[(size_t)row * DD + c0] = o;
        }
    }
}

// ---------------------------------------------------------------------------
extern "C" void kernel_launch(void* const* d_in, const int* in_sizes, int n_in,
                              void* d_out, int out_size) {
    const float* hidden = (const float*)d_in[0];
    const int*   eidx   = (const int*)d_in[1];
    const float* eattr  = (const float*)d_in[2];
    const float* We     = (const float*)d_in[3];
    const float* be     = (const float*)d_in[4];
    const float* W1     = (const float*)d_in[5];
    const float* b1     = (const float*)d_in[6];
    const float* W2     = (const float*)d_in[7];
    const float* b2     = (const float*)d_in[8];
    const float* eps    = (const float*)d_in[9];
    float*       out    = (float*)d_out;

    // Resolve DEVICE address of g_h (host &g_h is the shadow symbol; on GB300
    // ATS makes dereferencing it silently "work" and read zeros).
    float* p_h = nullptr;
    cudaGetSymbolAddress((void**)&p_h, g_h);

    const int tot4 = (NN * DD) / 4;                 // 1.6M
    zero_kernel<<<(tot4 + 255) / 256, 256>>>();

    scatter_kernel<<<(NE * 32) / 256, 256>>>(hidden, eidx, eattr, We, be);

    int gblocks = (NN + 63) / 64;                   // 782
    gemm128_fused_kernel<<<gblocks, 256>>>(hidden, eps, W1, b1, p_h, NN);
    gemm128_kernel<<<gblocks, 256>>>(p_h, W2, b2, out, NN);
}

// round 7
// speedup vs baseline: 1.7570x; 1.1211x over previous
#include <cuda_runtime.h>
#include <cstdint>

#define NN 50000
#define NE 800000
#define DD 128

// scratch (static device globals — no allocation allowed)
__device__ float g_accum[NN * DD];   // scatter accumulator
__device__ float g_cnt[NN];          // in-degree counts
__device__ float g_h[NN * DD];       // after GEMM1 + relu

// ---- packed f32x2 helpers (base PTX ISA 8.6, sm_100+; NOT 'a'-gated) -------
__device__ __forceinline__ unsigned long long pack2(float lo, float hi) {
    unsigned long long r;
    asm("mov.b64 %0, {%1, %2};" : "=l"(r) : "f"(lo), "f"(hi));
    return r;
}
__device__ __forceinline__ void unpack2(float& lo, float& hi, unsigned long long v) {
    asm("mov.b64 {%0, %1}, %2;" : "=f"(lo), "=f"(hi) : "l"(v));
}
__device__ __forceinline__ void ffma2(unsigned long long& d, unsigned long long a,
                                      unsigned long long b) {
    asm("fma.rn.f32x2 %0, %1, %2, %0;" : "+l"(d) : "l"(a), "l"(b));
}

// ---------------------------------------------------------------------------
// K1: zero accumulator + counts
// ---------------------------------------------------------------------------
__global__ void zero_kernel() {
    int i = blockIdx.x * blockDim.x + threadIdx.x;
    const int tot4 = (NN * DD) / 4;   // 1.6M float4
    if (i < tot4) ((float4*)g_accum)[i] = make_float4(0.f, 0.f, 0.f, 0.f);
    if (i < NN)   g_cnt[i] = 0.f;
}

// ---------------------------------------------------------------------------
// K2: edge scatter. One warp per edge; lane -> 4 dims; red.v4 into accum.
// edge_index is int32 in memory (JAX x64-disabled downcasts int64 -> int32).
// ---------------------------------------------------------------------------
__global__ void scatter_kernel(const float* __restrict__ hidden,
                               const int* __restrict__ edge_index,
                               const float* __restrict__ edge_attr,
                               const float* __restrict__ We,
                               const float* __restrict__ be) {
    int gtid = blockIdx.x * blockDim.x + threadIdx.x;
    int e = gtid >> 5, lane = gtid & 31;
    if (e >= NE) return;

    int   src = __ldg(&edge_index[e]);
    int   dst = __ldg(&edge_index[NE + e]);
    float a   = __ldg(&edge_attr[e]);

    int d0 = lane * 4;
    float4 h = *(const float4*)&hidden[(size_t)src * DD + d0];
    float4 w = *(const float4*)&We[d0];
    float4 b = *(const float4*)&be[d0];

    float4 m;
    m.x = fmaxf(fmaf(a, w.x, b.x) + h.x, 0.f);
    m.y = fmaxf(fmaf(a, w.y, b.y) + h.y, 0.f);
    m.z = fmaxf(fmaf(a, w.z, b.z) + h.z, 0.f);
    m.w = fmaxf(fmaf(a, w.w, b.w) + h.w, 0.f);

    unsigned long long p =
        (unsigned long long)__cvta_generic_to_global(&g_accum[(size_t)dst * DD + d0]);
    asm volatile("red.global.add.v4.f32 [%0], {%1,%2,%3,%4};"
                 :: "l"(p), "f"(m.x), "f"(m.y), "f"(m.z), "f"(m.w) : "memory");

    if (lane == 0) atomicAdd(&g_cnt[dst], 1.0f);
}

// ---------------------------------------------------------------------------
// K3/K4: C = act(A @ W + bias) with packed FFMA2 inner loop.
// TILE_M=64, 256 threads, KT=32. Warp w -> rows w*8..+7 (as 4 row-pairs),
// lane l -> cols l*4..+3. A tile stored k-major (As2[k][row], pad 66) so a
// row-pair is one aligned ld.shared.v2.f32 = a ready f32x2 operand.
// FUSED: A_row = (1+eps)*hidden + accum/max(cnt,1) computed in the loader.
// ---------------------------------------------------------------------------
template <bool FUSED, bool RELU>
__global__ void gemm128_kernel(const float* __restrict__ Ain,
                               const float* __restrict__ eps,
                               const float* __restrict__ W,
                               const float* __restrict__ bias,
                               float* __restrict__ C, int M) {
    __shared__ float As2[32][66];     // k-major A tile (pad 66: even, conflict-shifted)
    __shared__ float Ws[32][128];

    int tid  = threadIdx.x;
    int warp = tid >> 5;
    int lane = tid & 31;
    int row0 = blockIdx.x * 64;
    int r0   = warp * 8;
    int c0   = lane * 4;

    float s = FUSED ? (1.0f + __ldg(&eps[0])) : 0.f;

    // acc[p][c]: rows (r0+2p, r0+2p+1) x col (c0+c), packed f32x2
    unsigned long long acc[4][4];
#pragma unroll
    for (int p = 0; p < 4; p++)
#pragma unroll
        for (int c = 0; c < 4; c++) acc[p][c] = 0ull;

    for (int kt = 0; kt < 4; kt++) {
        // load A tile: 64 rows x 32 k, store TRANSPOSED into As2[k][row]
#pragma unroll
        for (int idx = tid; idx < 512; idx += 256) {
            int r = idx >> 3, f = idx & 7;
            int grow = row0 + r;
            float4 v = make_float4(0.f, 0.f, 0.f, 0.f);
            if (grow < M) {
                size_t off = (size_t)grow * DD + kt * 32 + f * 4;
                v = *(const float4*)&Ain[off];
                if (FUSED) {
                    float inv = 1.0f / fmaxf(g_cnt[grow], 1.0f);
                    float4 a = *(const float4*)&g_accum[off];
                    v.x = fmaf(s, v.x, a.x * inv);
                    v.y = fmaf(s, v.y, a.y * inv);
                    v.z = fmaf(s, v.z, a.z * inv);
                    v.w = fmaf(s, v.w, a.w * inv);
                }
            }
            As2[f * 4 + 0][r] = v.x;
            As2[f * 4 + 1][r] = v.y;
            As2[f * 4 + 2][r] = v.z;
            As2[f * 4 + 3][r] = v.w;
        }
        // load W tile: 32 k-rows x 128 cols (1024 float4)
#pragma unroll
        for (int idx = tid; idx < 1024; idx += 256) {
            int r = idx >> 5, f = idx & 31;
            *(float4*)&Ws[r][f * 4] = *(const float4*)&W[(kt * 32 + r) * DD + f * 4];
        }
        __syncthreads();

#pragma unroll
        for (int kk = 0; kk < 32; kk++) {
            float4 b = *(float4*)&Ws[kk][c0];
            unsigned long long bb[4];
            bb[0] = pack2(b.x, b.x);
            bb[1] = pack2(b.y, b.y);
            bb[2] = pack2(b.z, b.z);
            bb[3] = pack2(b.w, b.w);
#pragma unroll
            for (int p = 0; p < 4; p++) {
                unsigned long long a2 =
                    *(const unsigned long long*)&As2[kk][r0 + 2 * p];
                ffma2(acc[p][0], a2, bb[0]);
                ffma2(acc[p][1], a2, bb[1]);
                ffma2(acc[p][2], a2, bb[2]);
                ffma2(acc[p][3], a2, bb[3]);
            }
        }
        __syncthreads();
    }

    float4 bb4 = *(const float4*)&bias[c0];
#pragma unroll
    for (int p = 0; p < 4; p++) {
        float lo[4], hi[4];
#pragma unroll
        for (int c = 0; c < 4; c++) unpack2(lo[c], hi[c], acc[p][c]);

        int rA = row0 + r0 + 2 * p;
        if (rA < M) {
            float4 o;
            o.x = lo[0] + bb4.x; o.y = lo[1] + bb4.y;
            o.z = lo[2] + bb4.z; o.w = lo[3] + bb4.w;
            if (RELU) {
                o.x = fmaxf(o.x, 0.f); o.y = fmaxf(o.y, 0.f);
                o.z = fmaxf(o.z, 0.f); o.w = fmaxf(o.w, 0.f);
            }
            *(float4*)&C[(size_t)rA * DD + c0] = o;
        }
        int rB = rA + 1;
        if (rB < M) {
            float4 o;
            o.x = hi[0] + bb4.x; o.y = hi[1] + bb4.y;
            o.z = hi[2] + bb4.z; o.w = hi[3] + bb4.w;
            if (RELU) {
                o.x = fmaxf(o.x, 0.f); o.y = fmaxf(o.y, 0.f);
                o.z = fmaxf(o.z, 0.f); o.w = fmaxf(o.w, 0.f);
            }
            *(float4*)&C[(size_t)rB * DD + c0] = o;
        }
    }
}

// ---------------------------------------------------------------------------
extern "C" void kernel_launch(void* const* d_in, const int* in_sizes, int n_in,
                              void* d_out, int out_size) {
    const float* hidden = (const float*)d_in[0];
    const int*   eidx   = (const int*)d_in[1];
    const float* eattr  = (const float*)d_in[2];
    const float* We     = (const float*)d_in[3];
    const float* be     = (const float*)d_in[4];
    const float* W1     = (const float*)d_in[5];
    const float* b1     = (const float*)d_in[6];
    const float* W2     = (const float*)d_in[7];
    const float* b2     = (const float*)d_in[8];
    const float* eps    = (const float*)d_in[9];
    float*       out    = (float*)d_out;

    // DEVICE address of g_h (host &g_h is the ATS-readable shadow symbol!)
    float* p_h = nullptr;
    cudaGetSymbolAddress((void**)&p_h, g_h);

    const int tot4 = (NN * DD) / 4;
    zero_kernel<<<(tot4 + 255) / 256, 256>>>();
    scatter_kernel<<<(NE * 32) / 256, 256>>>(hidden, eidx, eattr, We, be);

    int gblocks = (NN + 63) / 64;   // 782
    gemm128_kernel<true,  true ><<<gblocks, 256>>>(hidden, eps, W1, b1, p_h, NN);
    gemm128_kernel<false, false><<<gblocks, 256>>>(p_h,    eps, W2, b2, out, NN);
}

// round 9
// speedup vs baseline: 1.8114x; 1.0309x over previous
#include <cuda_runtime.h>
#include <cstdint>

#define NN 50000
#define NE 800000
#define DD 128
#define NBLK 196   // ceil(50000/256)

// ------------------------- device scratch (no allocs) -----------------------
__device__ float g_accum[NN * DD];   // aggregated messages (sum)
__device__ float g_cnt[NN];          // in-degree (float, for GEMM1 fusion)
__device__ float g_h[NN * DD];       // after GEMM1 + relu
__device__ int   g_deg[NN];
__device__ int   g_off[NN];          // exclusive offsets
__device__ int   g_wptr[NN];         // fill cursors (init = g_off)
__device__ int   g_csr[NE];          // edge ids grouped by dst
__device__ int   g_bsum[NBLK];
__device__ int   g_boff[NBLK];

// ---- packed f32x2 helpers (base PTX ISA, sm_100+; not 'a'-gated) -----------
__device__ __forceinline__ unsigned long long pack2(float lo, float hi) {
    unsigned long long r;
    asm("mov.b64 %0, {%1, %2};" : "=l"(r) : "f"(lo), "f"(hi));
    return r;
}
__device__ __forceinline__ void unpack2(float& lo, float& hi, unsigned long long v) {
    asm("mov.b64 {%0, %1}, %2;" : "=f"(lo), "=f"(hi) : "l"(v));
}
__device__ __forceinline__ void ffma2(unsigned long long& d, unsigned long long a,
                                      unsigned long long b) {
    asm("fma.rn.f32x2 %0, %1, %2, %0;" : "+l"(d) : "l"(a), "l"(b));
}

// ---------------------------------------------------------------------------
// CSR build stage 0: zero degree counters
// ---------------------------------------------------------------------------
__global__ void zero_deg_kernel() {
    int i = blockIdx.x * blockDim.x + threadIdx.x;
    if (i < NN) g_deg[i] = 0;
}

// stage 1: histogram of dst
__global__ void hist_kernel(const int* __restrict__ edge_index) {
    int e = blockIdx.x * blockDim.x + threadIdx.x;
    if (e < NE) atomicAdd(&g_deg[__ldg(&edge_index[NE + e])], 1);
}

// stage 2: per-block sums of deg
__global__ void bsum_kernel() {
    __shared__ int s[256];
    int t = threadIdx.x;
    int i = blockIdx.x * 256 + t;
    s[t] = (i < NN) ? g_deg[i] : 0;
    __syncthreads();
    for (int off = 128; off > 0; off >>= 1) {
        if (t < off) s[t] += s[t + off];
        __syncthreads();
    }
    if (t == 0) g_bsum[blockIdx.x] = s[0];
}

// stage 3: serial exclusive scan of 196 block sums (single thread; trivial)
__global__ void scan_bsum_kernel() {
    int acc = 0;
    for (int i = 0; i < NBLK; i++) { g_boff[i] = acc; acc += g_bsum[i]; }
}

// stage 4: block-level exclusive scan -> g_off, g_wptr
__global__ void block_scan_kernel() {
    __shared__ int s[256];
    int t = threadIdx.x;
    int i = blockIdx.x * 256 + t;
    int v = (i < NN) ? g_deg[i] : 0;
    s[t] = v;
    __syncthreads();
    for (int off = 1; off < 256; off <<= 1) {
        int x = (t >= off) ? s[t - off] : 0;
        __syncthreads();
        s[t] += x;
        __syncthreads();
    }
    if (i < NN) {
        int excl = s[t] - v + g_boff[blockIdx.x];
        g_off[i]  = excl;
        g_wptr[i] = excl;
    }
}

// stage 5: fill CSR slots
__global__ void fill_kernel(const int* __restrict__ edge_index) {
    int e = blockIdx.x * blockDim.x + threadIdx.x;
    if (e < NE) {
        int dst = __ldg(&edge_index[NE + e]);
        int pos = atomicAdd(&g_wptr[dst], 1);
        g_csr[pos] = e;
    }
}

// ---------------------------------------------------------------------------
// Gather: one warp per dst node. Lane -> 4 dims. Walk edge list, accumulate
// relu(hidden[src] + a*We + be) in registers, write row once. No float atomics.
// ---------------------------------------------------------------------------
__global__ void gather_kernel(const float* __restrict__ hidden,
                              const int* __restrict__ edge_index,
                              const float* __restrict__ edge_attr,
                              const float* __restrict__ We,
                              const float* __restrict__ be) {
    int gtid = blockIdx.x * blockDim.x + threadIdx.x;
    int n = gtid >> 5, lane = gtid & 31;
    if (n >= NN) return;

    int deg  = g_deg[n];
    int base = g_off[n];
    int d0   = lane * 4;

    float4 w = *(const float4*)&We[d0];
    float4 b = *(const float4*)&be[d0];

    float4 acc = make_float4(0.f, 0.f, 0.f, 0.f);

    // software pipeline: resolve (src, a) for edge j+1 while accumulating j
    int src = 0; float a = 0.f;
    if (deg > 0) {
        int eid = __ldg(&g_csr[base]);
        src = __ldg(&edge_index[eid]);
        a   = __ldg(&edge_attr[eid]);
    }
    for (int j = 0; j < deg; j++) {
        float4 h = *(const float4*)&hidden[(size_t)src * DD + d0];
        int nsrc = 0; float na = 0.f;
        if (j + 1 < deg) {
            int eid = __ldg(&g_csr[base + j + 1]);
            nsrc = __ldg(&edge_index[eid]);
            na   = __ldg(&edge_attr[eid]);
        }
        acc.x += fmaxf(fmaf(a, w.x, b.x) + h.x, 0.f);
        acc.y += fmaxf(fmaf(a, w.y, b.y) + h.y, 0.f);
        acc.z += fmaxf(fmaf(a, w.z, b.z) + h.z, 0.f);
        acc.w += fmaxf(fmaf(a, w.w, b.w) + h.w, 0.f);
        src = nsrc; a = na;
    }

    *(float4*)&g_accum[(size_t)n * DD + d0] = acc;
    if (lane == 0) g_cnt[n] = (float)deg;
}

// ---------------------------------------------------------------------------
// GEMMs: C = act(A @ W + bias), packed FFMA2 inner loop (unchanged from R7).
// FUSED: A_row = (1+eps)*hidden + accum/max(cnt,1) in the loader.
// ---------------------------------------------------------------------------
template <bool FUSED, bool RELU>
__global__ void gemm128_kernel(const float* __restrict__ Ain,
                               const float* __restrict__ eps,
                               const float* __restrict__ W,
                               const float* __restrict__ bias,
                               float* __restrict__ C, int M) {
    __shared__ float As2[32][66];
    __shared__ float Ws[32][128];

    int tid  = threadIdx.x;
    int warp = tid >> 5;
    int lane = tid & 31;
    int row0 = blockIdx.x * 64;
    int r0   = warp * 8;
    int c0   = lane * 4;

    float s = FUSED ? (1.0f + __ldg(&eps[0])) : 0.f;

    unsigned long long acc[4][4];
#pragma unroll
    for (int p = 0; p < 4; p++)
#pragma unroll
        for (int c = 0; c < 4; c++) acc[p][c] = 0ull;

    for (int kt = 0; kt < 4; kt++) {
#pragma unroll
        for (int idx = tid; idx < 512; idx += 256) {
            int r = idx >> 3, f = idx & 7;
            int grow = row0 + r;
            float4 v = make_float4(0.f, 0.f, 0.f, 0.f);
            if (grow < M) {
                size_t off = (size_t)grow * DD + kt * 32 + f * 4;
                v = *(const float4*)&Ain[off];
                if (FUSED) {
                    float inv = 1.0f / fmaxf(g_cnt[grow], 1.0f);
                    float4 a = *(const float4*)&g_accum[off];
                    v.x = fmaf(s, v.x, a.x * inv);
                    v.y = fmaf(s, v.y, a.y * inv);
                    v.z = fmaf(s, v.z, a.z * inv);
                    v.w = fmaf(s, v.w, a.w * inv);
                }
            }
            As2[f * 4 + 0][r] = v.x;
            As2[f * 4 + 1][r] = v.y;
            As2[f * 4 + 2][r] = v.z;
            As2[f * 4 + 3][r] = v.w;
        }
#pragma unroll
        for (int idx = tid; idx < 1024; idx += 256) {
            int r = idx >> 5, f = idx & 31;
            *(float4*)&Ws[r][f * 4] = *(const float4*)&W[(kt * 32 + r) * DD + f * 4];
        }
        __syncthreads();

#pragma unroll
        for (int kk = 0; kk < 32; kk++) {
            float4 bv = *(float4*)&Ws[kk][c0];
            unsigned long long bb[4];
            bb[0] = pack2(bv.x, bv.x);
            bb[1] = pack2(bv.y, bv.y);
            bb[2] = pack2(bv.z, bv.z);
            bb[3] = pack2(bv.w, bv.w);
#pragma unroll
            for (int p = 0; p < 4; p++) {
                unsigned long long a2 =
                    *(const unsigned long long*)&As2[kk][r0 + 2 * p];
                ffma2(acc[p][0], a2, bb[0]);
                ffma2(acc[p][1], a2, bb[1]);
                ffma2(acc[p][2], a2, bb[2]);
                ffma2(acc[p][3], a2, bb[3]);
            }
        }
        __syncthreads();
    }

    float4 bb4 = *(const float4*)&bias[c0];
#pragma unroll
    for (int p = 0; p < 4; p++) {
        float lo[4], hi[4];
#pragma unroll
        for (int c = 0; c < 4; c++) unpack2(lo[c], hi[c], acc[p][c]);

        int rA = row0 + r0 + 2 * p;
        if (rA < M) {
            float4 o;
            o.x = lo[0] + bb4.x; o.y = lo[1] + bb4.y;
            o.z = lo[2] + bb4.z; o.w = lo[3] + bb4.w;
            if (RELU) {
                o.x = fmaxf(o.x, 0.f); o.y = fmaxf(o.y, 0.f);
                o.z = fmaxf(o.z, 0.f); o.w = fmaxf(o.w, 0.f);
            }
            *(float4*)&C[(size_t)rA * DD + c0] = o;
        }
        int rB = rA + 1;
        if (rB < M) {
            float4 o;
            o.x = hi[0] + bb4.x; o.y = hi[1] + bb4.y;
            o.z = hi[2] + bb4.z; o.w = hi[3] + bb4.w;
            if (RELU) {
                o.x = fmaxf(o.x, 0.f); o.y = fmaxf(o.y, 0.f);
                o.z = fmaxf(o.z, 0.f); o.w = fmaxf(o.w, 0.f);
            }
            *(float4*)&C[(size_t)rB * DD + c0] = o;
        }
    }
}

// ---------------------------------------------------------------------------
extern "C" void kernel_launch(void* const* d_in, const int* in_sizes, int n_in,
                              void* d_out, int out_size) {
    const float* hidden = (const float*)d_in[0];
    const int*   eidx   = (const int*)d_in[1];
    const float* eattr  = (const float*)d_in[2];
    const float* We     = (const float*)d_in[3];
    const float* be     = (const float*)d_in[4];
    const float* W1     = (const float*)d_in[5];
    const float* b1     = (const float*)d_in[6];
    const float* W2     = (const float*)d_in[7];
    const float* b2     = (const float*)d_in[8];
    const float* eps    = (const float*)d_in[9];
    float*       out    = (float*)d_out;

    // DEVICE address of g_h (host &g_h is the ATS-readable shadow symbol!)
    float* p_h = nullptr;
    cudaGetSymbolAddress((void**)&p_h, g_h);

    // --- CSR build ---
    zero_deg_kernel<<<NBLK, 256>>>();
    hist_kernel<<<(NE + 255) / 256, 256>>>(eidx);
    bsum_kernel<<<NBLK, 256>>>();
    scan_bsum_kernel<<<1, 1>>>();
    block_scan_kernel<<<NBLK, 256>>>();
    fill_kernel<<<(NE + 255) / 256, 256>>>(eidx);

    // --- gather (no float atomics) ---
    gather_kernel<<<(NN * 32 + 255) / 256, 256>>>(hidden, eidx, eattr, We, be);

    // --- MLP ---
    int gblocks = (NN + 63) / 64;   // 782
    gemm128_kernel<true,  true ><<<gblocks, 256>>>(hidden, eps, W1, b1, p_h, NN);
    gemm128_kernel<false, false><<<gblocks, 256>>>(p_h,    eps, W2, b2, out, NN);
}